// round 4
// baseline (speedup 1.0000x reference)
#include <cuda_runtime.h>

#define D_MODEL 1024
#define HEADS   16
#define DK      64
#define BATCH   2
#define SEQ     2048
#define M_TOK   (BATCH * SEQ)

// ---------------- scratch (static device globals; no runtime alloc) ----------
__device__ float g_qh[BATCH * HEADS * SEQ * DK];   // [B,H,S,Dk]
__device__ float g_kh[BATCH * HEADS * SEQ * DK];
__device__ float g_vh[BATCH * HEADS * SEQ * DK];
__device__ float g_ctx[BATCH * SEQ * D_MODEL];     // [B,S,D_MODEL] (concat layout)

// ---------------- GEMM: C = A[M,K] * W[N,K]^T + bias ------------------------
// BM=BN=128, BK=16, 8x8 per thread, 256 threads.
// mode 0/1/2 -> write g_qh/g_kh/g_vh in [B,H,S,Dk] head layout
// mode 3     -> write Cflat in flat [M, N] layout
#define BM  128
#define BN  128
#define BKK 16

__global__ __launch_bounds__(256) void sgemm_bias_k(
    const float* __restrict__ A, const float* __restrict__ W,
    const float* __restrict__ bias, float* __restrict__ Cflat, int mode)
{
    __shared__ float As[BKK][BM + 4];
    __shared__ float Ws[BKK][BN + 4];

    const float* Asrc = A ? A : g_ctx;

    int tid = threadIdx.x;
    int tx = tid & 15, ty = tid >> 4;
    int m0 = blockIdx.y * BM, n0 = blockIdx.x * BN;

    float acc[8][8];
#pragma unroll
    for (int i = 0; i < 8; i++)
#pragma unroll
        for (int j = 0; j < 8; j++) acc[i][j] = 0.f;

    for (int kt = 0; kt < D_MODEL; kt += BKK) {
#pragma unroll
        for (int l = 0; l < 2; l++) {
            int id  = tid + l * 256;
            int row = id >> 2;
            int kq  = (id & 3) << 2;
            float4 a = *(const float4*)&Asrc[(size_t)(m0 + row) * D_MODEL + kt + kq];
            As[kq + 0][row] = a.x; As[kq + 1][row] = a.y;
            As[kq + 2][row] = a.z; As[kq + 3][row] = a.w;
            float4 w = *(const float4*)&W[(size_t)(n0 + row) * D_MODEL + kt + kq];
            Ws[kq + 0][row] = w.x; Ws[kq + 1][row] = w.y;
            Ws[kq + 2][row] = w.z; Ws[kq + 3][row] = w.w;
        }
        __syncthreads();
#pragma unroll
        for (int kk = 0; kk < BKK; kk++) {
            float a[8], b[8];
#pragma unroll
            for (int i = 0; i < 8; i++) a[i] = As[kk][ty * 8 + i];
#pragma unroll
            for (int j = 0; j < 8; j++) b[j] = Ws[kk][tx * 8 + j];
#pragma unroll
            for (int i = 0; i < 8; i++)
#pragma unroll
                for (int j = 0; j < 8; j++) acc[i][j] += a[i] * b[j];
        }
        __syncthreads();
    }

    float* Cdst = (mode == 0) ? g_qh : (mode == 1) ? g_kh : (mode == 2) ? g_vh : Cflat;

#pragma unroll
    for (int i = 0; i < 8; i++) {
        int m = m0 + ty * 8 + i;
#pragma unroll
        for (int j = 0; j < 8; j++) {
            int n = n0 + tx * 8 + j;
            float v = acc[i][j] + bias[n];
            if (mode < 3) {
                int b_ = m >> 11, s = m & (SEQ - 1);
                int h  = n >> 6,  d = n & 63;
                Cdst[((size_t)(b_ * HEADS + h) * SEQ + s) * DK + d] = v;
            } else {
                Cdst[(size_t)m * D_MODEL + n] = v;
            }
        }
    }
}

// ---------------- flash attention (fp32, online softmax) --------------------
// grid: (SEQ/32, B*HEADS). 256 threads = 8 warps; each warp owns 4 q-rows.
// Each lane owns one key of the current 32-key tile.
#define QROWS 32
#define KTILE 32
#define TQ    4

__global__ __launch_bounds__(256) void flash_attn_k()
{
    __shared__ float Qs[QROWS][DK];          // 8 KB
    __shared__ float Kst[DK][KTILE + 1];     // transposed K tile, 8.25 KB
    __shared__ float Vs[KTILE][DK];          // 8 KB

    int tid  = threadIdx.x;
    int lane = tid & 31, w = tid >> 5;
    int bh = blockIdx.y;                 // 0..31
    int b  = bh >> 4, h = bh & 15;
    int qbase = blockIdx.x * QROWS;

    const float* Qp = g_qh + (size_t)bh * SEQ * DK;
    const float* Kp = g_kh + (size_t)bh * SEQ * DK;
    const float* Vp = g_vh + (size_t)bh * SEQ * DK;

    // stage Q tile
#pragma unroll
    for (int l = 0; l < 2; l++) {
        int id  = tid + l * 256;
        int row = id >> 4;
        int dq  = (id & 15) << 2;
        *(float4*)&Qs[row][dq] = *(const float4*)&Qp[(size_t)(qbase + row) * DK + dq];
    }

    int rw = w * TQ;
    float m[TQ], lsum[TQ], o0[TQ], o1[TQ];
#pragma unroll
    for (int r = 0; r < TQ; r++) { m[r] = -1e30f; lsum[r] = 0.f; o0[r] = 0.f; o1[r] = 0.f; }

    const float scale = 0.125f;   // 1/sqrt(DK)

    for (int kt = 0; kt < SEQ; kt += KTILE) {
        __syncthreads();
        // stage K (transposed) and V tiles
#pragma unroll
        for (int l = 0; l < 2; l++) {
            int id  = tid + l * 256;
            int key = id >> 4;
            int dq  = (id & 15) << 2;
            float4 kv = *(const float4*)&Kp[(size_t)(kt + key) * DK + dq];
            Kst[dq + 0][key] = kv.x; Kst[dq + 1][key] = kv.y;
            Kst[dq + 2][key] = kv.z; Kst[dq + 3][key] = kv.w;
            *(float4*)&Vs[key][dq] = *(const float4*)&Vp[(size_t)(kt + key) * DK + dq];
        }
        __syncthreads();

        // scores: lane <-> key(lane)
        float sc[TQ];
#pragma unroll
        for (int r = 0; r < TQ; r++) sc[r] = 0.f;
#pragma unroll
        for (int d4 = 0; d4 < DK / 4; d4++) {
            float k0 = Kst[d4 * 4 + 0][lane];
            float k1 = Kst[d4 * 4 + 1][lane];
            float k2 = Kst[d4 * 4 + 2][lane];
            float k3 = Kst[d4 * 4 + 3][lane];
#pragma unroll
            for (int r = 0; r < TQ; r++) {
                float4 q4 = *(const float4*)&Qs[rw + r][d4 * 4];
                sc[r] += q4.x * k0 + q4.y * k1 + q4.z * k2 + q4.w * k3;
            }
        }

        // online softmax (per q-row, across the 32 keys of this tile)
        float p[TQ];
#pragma unroll
        for (int r = 0; r < TQ; r++) {
            float s  = sc[r] * scale;
            float mt = s;
#pragma unroll
            for (int off = 16; off > 0; off >>= 1)
                mt = fmaxf(mt, __shfl_xor_sync(0xffffffffu, mt, off));
            float mn    = fmaxf(m[r], mt);
            float alpha = __expf(m[r] - mn);
            float pv    = __expf(s - mn);
            float psum  = pv;
#pragma unroll
            for (int off = 16; off > 0; off >>= 1)
                psum += __shfl_xor_sync(0xffffffffu, psum, off);
            lsum[r] = lsum[r] * alpha + psum;
            m[r]    = mn;
            o0[r] *= alpha; o1[r] *= alpha;
            p[r] = pv;
        }

        // P * V: broadcast p via shfl; lane accumulates d=lane and d=lane+32
#pragma unroll
        for (int j = 0; j < KTILE; j++) {
            float v0 = Vs[j][lane];
            float v1 = Vs[j][lane + 32];
#pragma unroll
            for (int r = 0; r < TQ; r++) {
                float pj = __shfl_sync(0xffffffffu, p[r], j);
                o0[r] += pj * v0;
                o1[r] += pj * v1;
            }
        }
    }

    // write ctx in concat layout [B,S,H*DK]
#pragma unroll
    for (int r = 0; r < TQ; r++) {
        int s = qbase + rw + r;
        float inv = 1.f / lsum[r];
        float* dst = g_ctx + (size_t)(b * SEQ + s) * D_MODEL + h * DK;
        dst[lane]      = o0[r] * inv;
        dst[lane + 32] = o1[r] * inv;
    }
}

// ---------------- launch ----------------------------------------------------
extern "C" void kernel_launch(void* const* d_in, const int* in_sizes, int n_in,
                              void* d_out, int out_size)
{
    const float* q  = (const float*)d_in[0];
    const float* k  = (const float*)d_in[1];
    const float* v  = (const float*)d_in[2];
    const float* wq = (const float*)d_in[3];
    const float* bq = (const float*)d_in[4];
    const float* wk = (const float*)d_in[5];
    const float* bk = (const float*)d_in[6];
    const float* wv = (const float*)d_in[7];
    const float* bv = (const float*)d_in[8];
    const float* wo = (const float*)d_in[9];
    const float* bo = (const float*)d_in[10];
    float* out = (float*)d_out;

    dim3 gemm_grid(D_MODEL / BN, M_TOK / BM);   // (8, 32)

    sgemm_bias_k<<<gemm_grid, 256>>>(q, wq, bq, nullptr, 0);
    sgemm_bias_k<<<gemm_grid, 256>>>(k, wk, bk, nullptr, 1);
    sgemm_bias_k<<<gemm_grid, 256>>>(v, wv, bv, nullptr, 2);

    flash_attn_k<<<dim3(SEQ / QROWS, BATCH * HEADS), 256>>>();

    sgemm_bias_k<<<gemm_grid, 256>>>(nullptr, wo, bo, out, 3);
}

// round 6
// speedup vs baseline: 1.2951x; 1.2951x over previous
#include <cuda_runtime.h>

#define D_MODEL 1024
#define HEADS   16
#define DK      64
#define BATCH   2
#define SEQ     2048
#define M_TOK   (BATCH * SEQ)

// ---------------- scratch (static device globals; no runtime alloc) ----------
__device__ float g_qh[BATCH * HEADS * SEQ * DK];   // [B,H,S,Dk]
__device__ float g_kh[BATCH * HEADS * SEQ * DK];
__device__ float g_vh[BATCH * HEADS * SEQ * DK];
__device__ float g_ctx[BATCH * SEQ * D_MODEL];     // [B,S,D_MODEL] (concat layout)

// ---------------- GEMM: C = A[M,K] * W[N,K]^T + bias ------------------------
#define BM  128
#define BN  128
#define BKK 16

__global__ __launch_bounds__(256) void sgemm_bias_k(
    const float* __restrict__ A, const float* __restrict__ W,
    const float* __restrict__ bias, float* __restrict__ Cflat, int mode)
{
    __shared__ float As[BKK][BM + 4];
    __shared__ float Ws[BKK][BN + 4];

    const float* Asrc = A ? A : g_ctx;

    int tid = threadIdx.x;
    int tx = tid & 15, ty = tid >> 4;
    int m0 = blockIdx.y * BM, n0 = blockIdx.x * BN;

    float acc[8][8];
#pragma unroll
    for (int i = 0; i < 8; i++)
#pragma unroll
        for (int j = 0; j < 8; j++) acc[i][j] = 0.f;

    for (int kt = 0; kt < D_MODEL; kt += BKK) {
#pragma unroll
        for (int l = 0; l < 2; l++) {
            int id  = tid + l * 256;
            int row = id >> 2;
            int kq  = (id & 3) << 2;
            float4 a = *(const float4*)&Asrc[(size_t)(m0 + row) * D_MODEL + kt + kq];
            As[kq + 0][row] = a.x; As[kq + 1][row] = a.y;
            As[kq + 2][row] = a.z; As[kq + 3][row] = a.w;
            float4 w = *(const float4*)&W[(size_t)(n0 + row) * D_MODEL + kt + kq];
            Ws[kq + 0][row] = w.x; Ws[kq + 1][row] = w.y;
            Ws[kq + 2][row] = w.z; Ws[kq + 3][row] = w.w;
        }
        __syncthreads();
#pragma unroll
        for (int kk = 0; kk < BKK; kk++) {
            float a[8], b[8];
#pragma unroll
            for (int i = 0; i < 8; i++) a[i] = As[kk][ty * 8 + i];
#pragma unroll
            for (int j = 0; j < 8; j++) b[j] = Ws[kk][tx * 8 + j];
#pragma unroll
            for (int i = 0; i < 8; i++)
#pragma unroll
                for (int j = 0; j < 8; j++) acc[i][j] += a[i] * b[j];
        }
        __syncthreads();
    }

    float* Cdst = (mode == 0) ? g_qh : (mode == 1) ? g_kh : (mode == 2) ? g_vh : Cflat;

#pragma unroll
    for (int i = 0; i < 8; i++) {
        int m = m0 + ty * 8 + i;
#pragma unroll
        for (int j = 0; j < 8; j++) {
            int n = n0 + tx * 8 + j;
            float v = acc[i][j] + bias[n];
            if (mode < 3) {
                int b_ = m >> 11, s = m & (SEQ - 1);
                int h  = n >> 6,  d = n & 63;
                Cdst[((size_t)(b_ * HEADS + h) * SEQ + s) * DK + d] = v;
            } else {
                Cdst[(size_t)m * D_MODEL + n] = v;
            }
        }
    }
}

// ---------------- flash attention v2: register-tiled, FMA-bound -------------
// Block: 64 q-rows, 64-key tiles, 256 threads as 16x16.
// Thread (tx,ty) owns S/O fragment rows ty*4+i, cols tx+16*j (strided cols ->
// conflict-free b-operand LDS.128 with stride-68 padding).
// Smem: Qs[64][68], Ks[64][68] (aliased by Ps after scores), Vst[64][68] (V^T).
#define BQ   64
#define BKT  64
#define STR  68   // row stride in floats: 68*4B -> row advances 16 bytes mod 128

__global__ __launch_bounds__(256) void flash_attn2_k()
{
    extern __shared__ float sm[];
    float* Qs  = sm;                    // [BQ][STR]
    float* Ks  = sm + BQ * STR;         // [BKT][STR]  (keys x d)
    float* Vst = sm + 2 * BQ * STR;     // [DK][STR]   (d x keys, transposed)
    float* Ps  = Ks;                    // alias: P tile overwrites K tile

    int tid = threadIdx.x;
    int tx  = tid & 15, ty = tid >> 4;
    int bh  = blockIdx.y;               // 0..31
    int b   = bh >> 4, h = bh & 15;
    int qbase = blockIdx.x * BQ;

    const float* Qp = g_qh + (size_t)bh * SEQ * DK;
    const float* Kp = g_kh + (size_t)bh * SEQ * DK;
    const float* Vp = g_vh + (size_t)bh * SEQ * DK;

    // stage Q tile, scale folded in (1/sqrt(64) = 0.125)
#pragma unroll
    for (int l = 0; l < 4; l++) {
        int id  = tid + l * 256;
        int row = id >> 4;
        int dq  = (id & 15) << 2;
        float4 q4 = *(const float4*)&Qp[(size_t)(qbase + row) * DK + dq];
        q4.x *= 0.125f; q4.y *= 0.125f; q4.z *= 0.125f; q4.w *= 0.125f;
        *(float4*)&Qs[row * STR + dq] = q4;
    }

    const int row0 = ty * 4;
    float m[4], lsum[4], o[4][4];
#pragma unroll
    for (int i = 0; i < 4; i++) {
        m[i] = -1e30f; lsum[i] = 0.f;
#pragma unroll
        for (int j = 0; j < 4; j++) o[i][j] = 0.f;
    }

    for (int kt = 0; kt < SEQ; kt += BKT) {
        __syncthreads();   // prev PV reads of Ps/Vst done; Q staging done (1st iter)

        // stage K tile [key][d]
#pragma unroll
        for (int l = 0; l < 4; l++) {
            int id  = tid + l * 256;
            int key = id >> 4;
            int dq  = (id & 15) << 2;
            *(float4*)&Ks[key * STR + dq] =
                *(const float4*)&Kp[(size_t)(kt + key) * DK + dq];
        }
        // stage V transposed [d][key]
#pragma unroll
        for (int l = 0; l < 4; l++) {
            int id  = tid + l * 256;
            int key = id & 63;
            int d   = (id >> 6) << 2;
            float4 v4 = *(const float4*)&Vp[(size_t)(kt + key) * DK + d];
            Vst[(d + 0) * STR + key] = v4.x;
            Vst[(d + 1) * STR + key] = v4.y;
            Vst[(d + 2) * STR + key] = v4.z;
            Vst[(d + 3) * STR + key] = v4.w;
        }
        __syncthreads();

        // ---- S = (Q*scale) . K^T : 4x4 register GEMM over d ----
        float acc[4][4];
#pragma unroll
        for (int i = 0; i < 4; i++)
#pragma unroll
            for (int j = 0; j < 4; j++) acc[i][j] = 0.f;

#pragma unroll
        for (int d4 = 0; d4 < DK / 4; d4++) {
            float4 a[4], bb[4];
#pragma unroll
            for (int i = 0; i < 4; i++)
                a[i] = *(const float4*)&Qs[(row0 + i) * STR + d4 * 4];
#pragma unroll
            for (int j = 0; j < 4; j++)
                bb[j] = *(const float4*)&Ks[(tx + 16 * j) * STR + d4 * 4];
#pragma unroll
            for (int i = 0; i < 4; i++)
#pragma unroll
                for (int j = 0; j < 4; j++)
                    acc[i][j] += a[i].x * bb[j].x + a[i].y * bb[j].y
                               + a[i].z * bb[j].z + a[i].w * bb[j].w;
        }

        // ---- online softmax (row group = 16 lanes sharing ty) ----
#pragma unroll
        for (int i = 0; i < 4; i++) {
            float mx = fmaxf(fmaxf(acc[i][0], acc[i][1]), fmaxf(acc[i][2], acc[i][3]));
#pragma unroll
            for (int off = 8; off > 0; off >>= 1)
                mx = fmaxf(mx, __shfl_xor_sync(0xffffffffu, mx, off));
            float mn = fmaxf(m[i], mx);
            float al = __expf(m[i] - mn);
            m[i] = mn;
            float rs = 0.f;
#pragma unroll
            for (int j = 0; j < 4; j++) {
                acc[i][j] = __expf(acc[i][j] - mn);
                rs += acc[i][j];
            }
#pragma unroll
            for (int off = 8; off > 0; off >>= 1)
                rs += __shfl_xor_sync(0xffffffffu, rs, off);
            lsum[i] = lsum[i] * al + rs;
#pragma unroll
            for (int j = 0; j < 4; j++) o[i][j] *= al;
        }

        __syncthreads();   // everyone done reading Ks before P overwrites it
#pragma unroll
        for (int i = 0; i < 4; i++)
#pragma unroll
            for (int j = 0; j < 4; j++)
                Ps[(row0 + i) * STR + tx + 16 * j] = acc[i][j];
        __syncthreads();

        // ---- O += P . V : 4x4 register GEMM over keys ----
#pragma unroll
        for (int k4 = 0; k4 < BKT / 4; k4++) {
            float4 a[4], bb[4];
#pragma unroll
            for (int i = 0; i < 4; i++)
                a[i] = *(const float4*)&Ps[(row0 + i) * STR + k4 * 4];
#pragma unroll
            for (int j = 0; j < 4; j++)
                bb[j] = *(const float4*)&Vst[(tx + 16 * j) * STR + k4 * 4];
#pragma unroll
            for (int i = 0; i < 4; i++)
#pragma unroll
                for (int j = 0; j < 4; j++)
                    o[i][j] += a[i].x * bb[j].x + a[i].y * bb[j].y
                             + a[i].z * bb[j].z + a[i].w * bb[j].w;
        }
    }

    // epilogue: normalize and write concat layout [B,S,H*DK]
#pragma unroll
    for (int i = 0; i < 4; i++) {
        int s = qbase + row0 + i;
        float inv = 1.f / lsum[i];
        float* dst = g_ctx + (size_t)(b * SEQ + s) * D_MODEL + h * DK;
#pragma unroll
        for (int j = 0; j < 4; j++)
            dst[tx + 16 * j] = o[i][j] * inv;
    }
}

// ---------------- launch ----------------------------------------------------
extern "C" void kernel_launch(void* const* d_in, const int* in_sizes, int n_in,
                              void* d_out, int out_size)
{
    const float* q  = (const float*)d_in[0];
    const float* k  = (const float*)d_in[1];
    const float* v  = (const float*)d_in[2];
    const float* wq = (const float*)d_in[3];
    const float* bq = (const float*)d_in[4];
    const float* wk = (const float*)d_in[5];
    const float* bk = (const float*)d_in[6];
    const float* wv = (const float*)d_in[7];
    const float* bv = (const float*)d_in[8];
    const float* wo = (const float*)d_in[9];
    const float* bo = (const float*)d_in[10];
    float* out = (float*)d_out;

    dim3 gemm_grid(D_MODEL / BN, M_TOK / BM);   // (8, 32)

    sgemm_bias_k<<<gemm_grid, 256>>>(q, wq, bq, nullptr, 0);
    sgemm_bias_k<<<gemm_grid, 256>>>(k, wk, bk, nullptr, 1);
    sgemm_bias_k<<<gemm_grid, 256>>>(v, wv, bv, nullptr, 2);

    const int smem_bytes = 3 * BQ * STR * (int)sizeof(float);   // 52224
    cudaFuncSetAttribute(flash_attn2_k,
                         cudaFuncAttributeMaxDynamicSharedMemorySize, smem_bytes);
    flash_attn2_k<<<dim3(SEQ / BQ, BATCH * HEADS), 256, smem_bytes>>>();

    sgemm_bias_k<<<gemm_grid, 256>>>(nullptr, wo, bo, out, 3);
}

// round 7
// speedup vs baseline: 1.7565x; 1.3562x over previous
#include <cuda_runtime.h>
#include <cuda_bf16.h>
#include <stdint.h>

#define D_MODEL 1024
#define HEADS   16
#define DK      64
#define BATCH   2
#define SEQ     2048
#define M_TOK   (BATCH * SEQ)

// ---------------- scratch (static device globals; no runtime alloc) ----------
__device__ float g_qh[BATCH * HEADS * SEQ * DK];   // [B,H,S,Dk]
__device__ float g_kh[BATCH * HEADS * SEQ * DK];
__device__ float g_vh[BATCH * HEADS * SEQ * DK];
__device__ float g_ctx[BATCH * SEQ * D_MODEL];     // [B,S,D_MODEL] (concat layout)

// ---------------- helpers ----------------------------------------------------
__device__ __forceinline__ uint16_t f2bf_bits(float x) {
    __nv_bfloat16 h = __float2bfloat16(x);
    return *reinterpret_cast<uint16_t*>(&h);
}
__device__ __forceinline__ float bfbits2f(uint16_t b) {
    __nv_bfloat16 h = *reinterpret_cast<__nv_bfloat16*>(&b);
    return __bfloat162float(h);
}
// split x into bf16 hi + bf16 lo (hi + lo represents x to ~2^-17 rel)
__device__ __forceinline__ void split_bf16(float x, uint16_t& hi, uint16_t& lo) {
    hi = f2bf_bits(x);
    lo = f2bf_bits(x - bfbits2f(hi));
}

__device__ __forceinline__ void mma16816(float* c, const uint32_t* a, const uint32_t* b) {
    asm volatile(
        "mma.sync.aligned.m16n8k16.row.col.f32.bf16.bf16.f32 "
        "{%0,%1,%2,%3}, {%4,%5,%6,%7}, {%8,%9}, {%0,%1,%2,%3};"
        : "+f"(c[0]), "+f"(c[1]), "+f"(c[2]), "+f"(c[3])
        : "r"(a[0]), "r"(a[1]), "r"(a[2]), "r"(a[3]), "r"(b[0]), "r"(b[1]));
}

// ---------------- split-bf16 tensor GEMM: C = A[M,K] * W[N,K]^T + bias ------
// BM=128, BN=128, BK=32. 256 threads = 8 warps as 2 (M) x 4 (N); warp tile 64x32.
// C ~= Ah*Wh + Ah*Wl + Al*Wh  (fp32 accumulate), rel err ~1e-5.
#define BM  128
#define BN  128
#define BK  32
#define BKP 40    // padded row stride (bf16 elems): 80 bytes -> conflict-free frags

__global__ __launch_bounds__(256, 2) void mma_gemm_bias_k(
    const float* __restrict__ A, const float* __restrict__ W,
    const float* __restrict__ bias, float* __restrict__ Cflat, int mode)
{
    __shared__ uint16_t Ahi[BM][BKP], Alo[BM][BKP];
    __shared__ uint16_t Whi[BN][BKP], Wlo[BN][BKP];

    const float* Asrc = A ? A : g_ctx;

    const int tid  = threadIdx.x;
    const int lane = tid & 31, w = tid >> 5;
    const int wm = w & 1, wn = w >> 1;          // warp grid 2 x 4
    const int g  = lane >> 2, tq = lane & 3;    // fragment group / quad
    const int m0 = blockIdx.y * BM, n0 = blockIdx.x * BN;

    float acc[4][4][4];                         // [mi][ni][reg]
#pragma unroll
    for (int mi = 0; mi < 4; mi++)
#pragma unroll
        for (int ni = 0; ni < 4; ni++)
#pragma unroll
            for (int r = 0; r < 4; r++) acc[mi][ni][r] = 0.f;

    for (int kt = 0; kt < D_MODEL; kt += BK) {
        __syncthreads();
        // stage + convert: each thread handles 4 float4 (2 for A, 2 for W)
#pragma unroll
        for (int l = 0; l < 2; l++) {
            int id  = tid + l * 256;
            int row = id >> 3;                  // 0..63  (two passes cover 128 rows? no:)
            // 512 ids cover 128 rows x 4 chunks: row = id/4? Recompute:
            // 128 rows * (32/4=8 chunks) = 1024 chunks / 256 thr = 4 chunks per thread.
            (void)row;
        }
        // A tile: 128 rows x 32 k = 1024 float4-chunks? (128*8=1024) -> 4 per thread
#pragma unroll
        for (int l = 0; l < 4; l++) {
            int id  = tid + l * 256;
            int row = id >> 3;
            int kq  = (id & 7) << 2;
            float4 a = *(const float4*)&Asrc[(size_t)(m0 + row) * D_MODEL + kt + kq];
            uint16_t h0,l0,h1,l1,h2,l2,h3,l3;
            split_bf16(a.x, h0, l0); split_bf16(a.y, h1, l1);
            split_bf16(a.z, h2, l2); split_bf16(a.w, h3, l3);
            Ahi[row][kq+0]=h0; Ahi[row][kq+1]=h1; Ahi[row][kq+2]=h2; Ahi[row][kq+3]=h3;
            Alo[row][kq+0]=l0; Alo[row][kq+1]=l1; Alo[row][kq+2]=l2; Alo[row][kq+3]=l3;
            float4 wv = *(const float4*)&W[(size_t)(n0 + row) * D_MODEL + kt + kq];
            split_bf16(wv.x, h0, l0); split_bf16(wv.y, h1, l1);
            split_bf16(wv.z, h2, l2); split_bf16(wv.w, h3, l3);
            Whi[row][kq+0]=h0; Whi[row][kq+1]=h1; Whi[row][kq+2]=h2; Whi[row][kq+3]=h3;
            Wlo[row][kq+0]=l0; Wlo[row][kq+1]=l1; Wlo[row][kq+2]=l2; Wlo[row][kq+3]=l3;
        }
        __syncthreads();

#pragma unroll
        for (int s = 0; s < 2; s++) {           // two k16 steps per BK=32
            const int kb = s * 16 + tq * 2;

            // B fragments for all 4 n8 blocks (hi & lo)
            uint32_t bh[4][2], bl[4][2];
#pragma unroll
            for (int ni = 0; ni < 4; ni++) {
                int n = wn * 32 + ni * 8 + g;
                bh[ni][0] = *(const uint32_t*)&Whi[n][kb];
                bh[ni][1] = *(const uint32_t*)&Whi[n][kb + 8];
                bl[ni][0] = *(const uint32_t*)&Wlo[n][kb];
                bl[ni][1] = *(const uint32_t*)&Wlo[n][kb + 8];
            }

#pragma unroll
            for (int mi = 0; mi < 4; mi++) {
                int r0 = wm * 64 + mi * 16 + g;
                uint32_t ah[4], al[4];
                ah[0] = *(const uint32_t*)&Ahi[r0    ][kb];
                ah[1] = *(const uint32_t*)&Ahi[r0 + 8][kb];
                ah[2] = *(const uint32_t*)&Ahi[r0    ][kb + 8];
                ah[3] = *(const uint32_t*)&Ahi[r0 + 8][kb + 8];
                al[0] = *(const uint32_t*)&Alo[r0    ][kb];
                al[1] = *(const uint32_t*)&Alo[r0 + 8][kb];
                al[2] = *(const uint32_t*)&Alo[r0    ][kb + 8];
                al[3] = *(const uint32_t*)&Alo[r0 + 8][kb + 8];
#pragma unroll
                for (int ni = 0; ni < 4; ni++) {
                    mma16816(acc[mi][ni], ah, bh[ni]);   // hi*hi
                    mma16816(acc[mi][ni], ah, bl[ni]);   // hi*lo
                    mma16816(acc[mi][ni], al, bh[ni]);   // lo*hi
                }
            }
        }
    }

    // epilogue
    float* Cdst = (mode == 0) ? g_qh : (mode == 1) ? g_kh : (mode == 2) ? g_vh : Cflat;

#pragma unroll
    for (int mi = 0; mi < 4; mi++) {
#pragma unroll
        for (int ni = 0; ni < 4; ni++) {
#pragma unroll
            for (int half = 0; half < 2; half++) {       // c0/c1 then c2/c3
                int m = m0 + wm * 64 + mi * 16 + g + half * 8;
#pragma unroll
                for (int cc = 0; cc < 2; cc++) {
                    int n = n0 + wn * 32 + ni * 8 + tq * 2 + cc;
                    float v = acc[mi][ni][half * 2 + cc] + bias[n];
                    if (mode < 3) {
                        int b_ = m >> 11, ss = m & (SEQ - 1);
                        int h  = n >> 6,  d  = n & 63;
                        Cdst[((size_t)(b_ * HEADS + h) * SEQ + ss) * DK + d] = v;
                    } else {
                        Cdst[(size_t)m * D_MODEL + n] = v;
                    }
                }
            }
        }
    }
}

// ---------------- flash attention v2: register-tiled, FMA-bound -------------
#define BQ   64
#define BKT  64
#define STR  68

__global__ __launch_bounds__(256) void flash_attn2_k()
{
    extern __shared__ float sm[];
    float* Qs  = sm;                    // [BQ][STR]
    float* Ks  = sm + BQ * STR;         // [BKT][STR]
    float* Vst = sm + 2 * BQ * STR;     // [DK][STR]
    float* Ps  = Ks;                    // alias

    int tid = threadIdx.x;
    int tx  = tid & 15, ty = tid >> 4;
    int bh  = blockIdx.y;
    int b   = bh >> 4, h = bh & 15;
    int qbase = blockIdx.x * BQ;

    const float* Qp = g_qh + (size_t)bh * SEQ * DK;
    const float* Kp = g_kh + (size_t)bh * SEQ * DK;
    const float* Vp = g_vh + (size_t)bh * SEQ * DK;

#pragma unroll
    for (int l = 0; l < 4; l++) {
        int id  = tid + l * 256;
        int row = id >> 4;
        int dq  = (id & 15) << 2;
        float4 q4 = *(const float4*)&Qp[(size_t)(qbase + row) * DK + dq];
        q4.x *= 0.125f; q4.y *= 0.125f; q4.z *= 0.125f; q4.w *= 0.125f;
        *(float4*)&Qs[row * STR + dq] = q4;
    }

    const int row0 = ty * 4;
    float m[4], lsum[4], o[4][4];
#pragma unroll
    for (int i = 0; i < 4; i++) {
        m[i] = -1e30f; lsum[i] = 0.f;
#pragma unroll
        for (int j = 0; j < 4; j++) o[i][j] = 0.f;
    }

    for (int kt = 0; kt < SEQ; kt += BKT) {
        __syncthreads();
#pragma unroll
        for (int l = 0; l < 4; l++) {
            int id  = tid + l * 256;
            int key = id >> 4;
            int dq  = (id & 15) << 2;
            *(float4*)&Ks[key * STR + dq] =
                *(const float4*)&Kp[(size_t)(kt + key) * DK + dq];
        }
#pragma unroll
        for (int l = 0; l < 4; l++) {
            int id  = tid + l * 256;
            int key = id & 63;
            int d   = (id >> 6) << 2;
            float4 v4 = *(const float4*)&Vp[(size_t)(kt + key) * DK + d];
            Vst[(d + 0) * STR + key] = v4.x;
            Vst[(d + 1) * STR + key] = v4.y;
            Vst[(d + 2) * STR + key] = v4.z;
            Vst[(d + 3) * STR + key] = v4.w;
        }
        __syncthreads();

        float acc[4][4];
#pragma unroll
        for (int i = 0; i < 4; i++)
#pragma unroll
            for (int j = 0; j < 4; j++) acc[i][j] = 0.f;

#pragma unroll
        for (int d4 = 0; d4 < DK / 4; d4++) {
            float4 a[4], bb[4];
#pragma unroll
            for (int i = 0; i < 4; i++)
                a[i] = *(const float4*)&Qs[(row0 + i) * STR + d4 * 4];
#pragma unroll
            for (int j = 0; j < 4; j++)
                bb[j] = *(const float4*)&Ks[(tx + 16 * j) * STR + d4 * 4];
#pragma unroll
            for (int i = 0; i < 4; i++)
#pragma unroll
                for (int j = 0; j < 4; j++)
                    acc[i][j] += a[i].x * bb[j].x + a[i].y * bb[j].y
                               + a[i].z * bb[j].z + a[i].w * bb[j].w;
        }

#pragma unroll
        for (int i = 0; i < 4; i++) {
            float mx = fmaxf(fmaxf(acc[i][0], acc[i][1]), fmaxf(acc[i][2], acc[i][3]));
#pragma unroll
            for (int off = 8; off > 0; off >>= 1)
                mx = fmaxf(mx, __shfl_xor_sync(0xffffffffu, mx, off));
            float mn = fmaxf(m[i], mx);
            float al = __expf(m[i] - mn);
            m[i] = mn;
            float rs = 0.f;
#pragma unroll
            for (int j = 0; j < 4; j++) {
                acc[i][j] = __expf(acc[i][j] - mn);
                rs += acc[i][j];
            }
#pragma unroll
            for (int off = 8; off > 0; off >>= 1)
                rs += __shfl_xor_sync(0xffffffffu, rs, off);
            lsum[i] = lsum[i] * al + rs;
#pragma unroll
            for (int j = 0; j < 4; j++) o[i][j] *= al;
        }

        __syncthreads();
#pragma unroll
        for (int i = 0; i < 4; i++)
#pragma unroll
            for (int j = 0; j < 4; j++)
                Ps[(row0 + i) * STR + tx + 16 * j] = acc[i][j];
        __syncthreads();

#pragma unroll
        for (int k4 = 0; k4 < BKT / 4; k4++) {
            float4 a[4], bb[4];
#pragma unroll
            for (int i = 0; i < 4; i++)
                a[i] = *(const float4*)&Ps[(row0 + i) * STR + k4 * 4];
#pragma unroll
            for (int j = 0; j < 4; j++)
                bb[j] = *(const float4*)&Vst[(tx + 16 * j) * STR + k4 * 4];
#pragma unroll
            for (int i = 0; i < 4; i++)
#pragma unroll
                for (int j = 0; j < 4; j++)
                    o[i][j] += a[i].x * bb[j].x + a[i].y * bb[j].y
                             + a[i].z * bb[j].z + a[i].w * bb[j].w;
        }
    }

#pragma unroll
    for (int i = 0; i < 4; i++) {
        int s = qbase + row0 + i;
        float inv = 1.f / lsum[i];
        float* dst = g_ctx + (size_t)(b * SEQ + s) * D_MODEL + h * DK;
#pragma unroll
        for (int j = 0; j < 4; j++)
            dst[tx + 16 * j] = o[i][j] * inv;
    }
}

// ---------------- launch ----------------------------------------------------
extern "C" void kernel_launch(void* const* d_in, const int* in_sizes, int n_in,
                              void* d_out, int out_size)
{
    const float* q  = (const float*)d_in[0];
    const float* k  = (const float*)d_in[1];
    const float* v  = (const float*)d_in[2];
    const float* wq = (const float*)d_in[3];
    const float* bq = (const float*)d_in[4];
    const float* wk = (const float*)d_in[5];
    const float* bk = (const float*)d_in[6];
    const float* wv = (const float*)d_in[7];
    const float* bv = (const float*)d_in[8];
    const float* wo = (const float*)d_in[9];
    const float* bo = (const float*)d_in[10];
    float* out = (float*)d_out;

    dim3 gemm_grid(D_MODEL / BN, M_TOK / BM);   // (8, 32)

    mma_gemm_bias_k<<<gemm_grid, 256>>>(q, wq, bq, nullptr, 0);
    mma_gemm_bias_k<<<gemm_grid, 256>>>(k, wk, bk, nullptr, 1);
    mma_gemm_bias_k<<<gemm_grid, 256>>>(v, wv, bv, nullptr, 2);

    const int smem_bytes = 3 * BQ * STR * (int)sizeof(float);   // 52224
    cudaFuncSetAttribute(flash_attn2_k,
                         cudaFuncAttributeMaxDynamicSharedMemorySize, smem_bytes);
    flash_attn2_k<<<dim3(SEQ / BQ, BATCH * HEADS), 256, smem_bytes>>>();

    mma_gemm_bias_k<<<gemm_grid, 256>>>(nullptr, wo, bo, out, 3);
}

// round 8
// speedup vs baseline: 3.3357x; 1.8991x over previous
#include <cuda_runtime.h>
#include <cuda_bf16.h>
#include <stdint.h>

#define D_MODEL 1024
#define HEADS   16
#define DK      64
#define BATCH   2
#define SEQ     2048
#define M_TOK   (BATCH * SEQ)
#define BH      (BATCH * HEADS)

// ---------------- scratch (static device globals; no runtime alloc) ----------
// split-bf16 projected tensors, [bh][s][d] (Q pre-scaled by 1/sqrt(dk))
__device__ uint16_t g_q_hi[BH * SEQ * DK], g_q_lo[BH * SEQ * DK];
__device__ uint16_t g_k_hi[BH * SEQ * DK], g_k_lo[BH * SEQ * DK];
__device__ uint16_t g_v_hi[BH * SEQ * DK], g_v_lo[BH * SEQ * DK];
// V transposed, [bh][d][s]
__device__ uint16_t g_vt_hi[BH * DK * SEQ], g_vt_lo[BH * DK * SEQ];
__device__ float    g_ctx[BATCH * SEQ * D_MODEL];   // attention output (concat)

// ---------------- helpers ----------------------------------------------------
__device__ __forceinline__ uint16_t f2bf_bits(float x) {
    __nv_bfloat16 h = __float2bfloat16(x);
    return *reinterpret_cast<uint16_t*>(&h);
}
__device__ __forceinline__ float bfbits2f(uint16_t b) {
    __nv_bfloat16 h = *reinterpret_cast<__nv_bfloat16*>(&b);
    return __bfloat162float(h);
}
__device__ __forceinline__ void split_bf16(float x, uint16_t& hi, uint16_t& lo) {
    hi = f2bf_bits(x);
    lo = f2bf_bits(x - bfbits2f(hi));
}
// split two floats and pack into u32 (low 16 = first elem)
__device__ __forceinline__ void split_pack2(float p0, float p1,
                                            uint32_t& hi, uint32_t& lo) {
    uint16_t h0, l0, h1, l1;
    split_bf16(p0, h0, l0);
    split_bf16(p1, h1, l1);
    hi = (uint32_t)h0 | ((uint32_t)h1 << 16);
    lo = (uint32_t)l0 | ((uint32_t)l1 << 16);
}

__device__ __forceinline__ void mma16816(float* c, const uint32_t* a, const uint32_t* b) {
    asm volatile(
        "mma.sync.aligned.m16n8k16.row.col.f32.bf16.bf16.f32 "
        "{%0,%1,%2,%3}, {%4,%5,%6,%7}, {%8,%9}, {%0,%1,%2,%3};"
        : "+f"(c[0]), "+f"(c[1]), "+f"(c[2]), "+f"(c[3])
        : "r"(a[0]), "r"(a[1]), "r"(a[2]), "r"(a[3]), "r"(b[0]), "r"(b[1]));
}

// ---------------- split-bf16 tensor GEMM: C = A[M,K] * W[N,K]^T + bias ------
// modes 0/1/2: write split-bf16 q/k/v in [bh][s][d]; mode 3: fp32 flat out.
#define BM  128
#define BN  128
#define BK  32
#define BKP 40

__global__ __launch_bounds__(256, 2) void mma_gemm_bias_k(
    const float* __restrict__ A, const float* __restrict__ W,
    const float* __restrict__ bias, float* __restrict__ Cflat, int mode)
{
    __shared__ uint16_t Ahi[BM][BKP], Alo[BM][BKP];
    __shared__ uint16_t Whi[BN][BKP], Wlo[BN][BKP];

    const float* Asrc = A ? A : g_ctx;

    const int tid  = threadIdx.x;
    const int lane = tid & 31, w = tid >> 5;
    const int wm = w & 1, wn = w >> 1;
    const int g  = lane >> 2, tq = lane & 3;
    const int m0 = blockIdx.y * BM, n0 = blockIdx.x * BN;

    float acc[4][4][4];
#pragma unroll
    for (int mi = 0; mi < 4; mi++)
#pragma unroll
        for (int ni = 0; ni < 4; ni++)
#pragma unroll
            for (int r = 0; r < 4; r++) acc[mi][ni][r] = 0.f;

    for (int kt = 0; kt < D_MODEL; kt += BK) {
        __syncthreads();
#pragma unroll
        for (int l = 0; l < 4; l++) {
            int id  = tid + l * 256;
            int row = id >> 3;
            int kq  = (id & 7) << 2;
            float4 a = *(const float4*)&Asrc[(size_t)(m0 + row) * D_MODEL + kt + kq];
            uint16_t h0,l0,h1,l1,h2,l2,h3,l3;
            split_bf16(a.x, h0, l0); split_bf16(a.y, h1, l1);
            split_bf16(a.z, h2, l2); split_bf16(a.w, h3, l3);
            Ahi[row][kq+0]=h0; Ahi[row][kq+1]=h1; Ahi[row][kq+2]=h2; Ahi[row][kq+3]=h3;
            Alo[row][kq+0]=l0; Alo[row][kq+1]=l1; Alo[row][kq+2]=l2; Alo[row][kq+3]=l3;
            float4 wv = *(const float4*)&W[(size_t)(n0 + row) * D_MODEL + kt + kq];
            split_bf16(wv.x, h0, l0); split_bf16(wv.y, h1, l1);
            split_bf16(wv.z, h2, l2); split_bf16(wv.w, h3, l3);
            Whi[row][kq+0]=h0; Whi[row][kq+1]=h1; Whi[row][kq+2]=h2; Whi[row][kq+3]=h3;
            Wlo[row][kq+0]=l0; Wlo[row][kq+1]=l1; Wlo[row][kq+2]=l2; Wlo[row][kq+3]=l3;
        }
        __syncthreads();

#pragma unroll
        for (int s = 0; s < 2; s++) {
            const int kb = s * 16 + tq * 2;
            uint32_t bhf[4][2], blf[4][2];
#pragma unroll
            for (int ni = 0; ni < 4; ni++) {
                int n = wn * 32 + ni * 8 + g;
                bhf[ni][0] = *(const uint32_t*)&Whi[n][kb];
                bhf[ni][1] = *(const uint32_t*)&Whi[n][kb + 8];
                blf[ni][0] = *(const uint32_t*)&Wlo[n][kb];
                blf[ni][1] = *(const uint32_t*)&Wlo[n][kb + 8];
            }
#pragma unroll
            for (int mi = 0; mi < 4; mi++) {
                int r0 = wm * 64 + mi * 16 + g;
                uint32_t ah[4], al[4];
                ah[0] = *(const uint32_t*)&Ahi[r0    ][kb];
                ah[1] = *(const uint32_t*)&Ahi[r0 + 8][kb];
                ah[2] = *(const uint32_t*)&Ahi[r0    ][kb + 8];
                ah[3] = *(const uint32_t*)&Ahi[r0 + 8][kb + 8];
                al[0] = *(const uint32_t*)&Alo[r0    ][kb];
                al[1] = *(const uint32_t*)&Alo[r0 + 8][kb];
                al[2] = *(const uint32_t*)&Alo[r0    ][kb + 8];
                al[3] = *(const uint32_t*)&Alo[r0 + 8][kb + 8];
#pragma unroll
                for (int ni = 0; ni < 4; ni++) {
                    mma16816(acc[mi][ni], ah, bhf[ni]);
                    mma16816(acc[mi][ni], ah, blf[ni]);
                    mma16816(acc[mi][ni], al, bhf[ni]);
                }
            }
        }
    }

    uint16_t* dsthi = (mode == 0) ? g_q_hi : (mode == 1) ? g_k_hi : g_v_hi;
    uint16_t* dstlo = (mode == 0) ? g_q_lo : (mode == 1) ? g_k_lo : g_v_lo;
    const float sc = (mode == 0) ? 0.125f : 1.0f;   // fold 1/sqrt(dk) into Q

#pragma unroll
    for (int mi = 0; mi < 4; mi++) {
#pragma unroll
        for (int ni = 0; ni < 4; ni++) {
#pragma unroll
            for (int half = 0; half < 2; half++) {
                int m = m0 + wm * 64 + mi * 16 + g + half * 8;
#pragma unroll
                for (int cc = 0; cc < 2; cc++) {
                    int n = n0 + wn * 32 + ni * 8 + tq * 2 + cc;
                    float v = acc[mi][ni][half * 2 + cc] + bias[n];
                    if (mode < 3) {
                        int b_ = m >> 11, ss = m & (SEQ - 1);
                        int h  = n >> 6,  d  = n & 63;
                        size_t idx = ((size_t)(b_ * HEADS + h) * SEQ + ss) * DK + d;
                        uint16_t vh, vl;
                        split_bf16(v * sc, vh, vl);
                        dsthi[idx] = vh; dstlo[idx] = vl;
                    } else {
                        Cflat[(size_t)m * D_MODEL + n] = v;
                    }
                }
            }
        }
    }
}

// ---------------- V transpose: [bh][s][d] -> [bh][d][s] ---------------------
__global__ __launch_bounds__(256) void vtrans_k()
{
    __shared__ uint16_t th[32][72], tl[32][72];
    int tid = threadIdx.x;
    int bh  = blockIdx.y;
    int s0  = blockIdx.x * 32;

    {
        int s  = tid >> 3;
        int dc = (tid & 7) << 3;
        size_t src = ((size_t)bh * SEQ + s0 + s) * DK + dc;
        *(uint4*)&th[s][dc] = *(const uint4*)&g_v_hi[src];
        *(uint4*)&tl[s][dc] = *(const uint4*)&g_v_lo[src];
    }
    __syncthreads();
    {
        int d  = tid >> 2;
        int sc = (tid & 3) << 3;
        size_t dst = ((size_t)bh * DK + d) * SEQ + s0 + sc;
#pragma unroll
        for (int i = 0; i < 4; i++) {
            uint32_t uh = (uint32_t)th[sc + 2*i][d] | ((uint32_t)th[sc + 2*i + 1][d] << 16);
            uint32_t ul = (uint32_t)tl[sc + 2*i][d] | ((uint32_t)tl[sc + 2*i + 1][d] << 16);
            *(uint32_t*)&g_vt_hi[dst + 2*i] = uh;
            *(uint32_t*)&g_vt_lo[dst + 2*i] = ul;
        }
    }
}

// ---------------- tensor-core flash attention (split bf16) ------------------
// 128 threads = 4 warps; warp w owns q rows [w*16, w*16+16). 64-key tiles.
#define FSTR 72   // smem row stride (bf16 elems): (4g+tq)%32 -> conflict-free frags

__global__ __launch_bounds__(128) void flash_mma_k()
{
    extern __shared__ uint16_t smu[];
    uint16_t* Qhi = smu;
    uint16_t* Qlo = Qhi + 64 * FSTR;
    uint16_t* Khi = Qlo + 64 * FSTR;
    uint16_t* Klo = Khi + 64 * FSTR;
    uint16_t* Vhi = Klo + 64 * FSTR;   // V^T tile: [d][key]
    uint16_t* Vlo = Vhi + 64 * FSTR;

    const int tid  = threadIdx.x;
    const int lane = tid & 31, w = tid >> 5;
    const int g = lane >> 2, tq = lane & 3;
    const int bh = blockIdx.y;
    const int b  = bh >> 4, h = bh & 15;
    const int qbase = blockIdx.x * 64;
    const int q0 = w * 16;

    // stage Q (already scaled by 1/sqrt(dk))
#pragma unroll
    for (int l = 0; l < 4; l++) {
        int id  = tid + l * 128;
        int row = id >> 3;
        int dc  = (id & 7) << 3;
        size_t src = ((size_t)bh * SEQ + qbase + row) * DK + dc;
        *(uint4*)&Qhi[row * FSTR + dc] = *(const uint4*)&g_q_hi[src];
        *(uint4*)&Qlo[row * FSTR + dc] = *(const uint4*)&g_q_lo[src];
    }
    __syncthreads();

    // Q fragments in registers (live across the whole k-loop)
    uint32_t aqh[4][4], aql[4][4];
#pragma unroll
    for (int t = 0; t < 4; t++) {
        int c0 = 16 * t + 2 * tq;
        aqh[t][0] = *(const uint32_t*)&Qhi[(q0 + g    ) * FSTR + c0];
        aqh[t][1] = *(const uint32_t*)&Qhi[(q0 + g + 8) * FSTR + c0];
        aqh[t][2] = *(const uint32_t*)&Qhi[(q0 + g    ) * FSTR + c0 + 8];
        aqh[t][3] = *(const uint32_t*)&Qhi[(q0 + g + 8) * FSTR + c0 + 8];
        aql[t][0] = *(const uint32_t*)&Qlo[(q0 + g    ) * FSTR + c0];
        aql[t][1] = *(const uint32_t*)&Qlo[(q0 + g + 8) * FSTR + c0];
        aql[t][2] = *(const uint32_t*)&Qlo[(q0 + g    ) * FSTR + c0 + 8];
        aql[t][3] = *(const uint32_t*)&Qlo[(q0 + g + 8) * FSTR + c0 + 8];
    }

    float m0 = -1e30f, m1 = -1e30f, l0 = 0.f, l1 = 0.f;
    float oacc[8][4];
#pragma unroll
    for (int dj = 0; dj < 8; dj++)
#pragma unroll
        for (int r = 0; r < 4; r++) oacc[dj][r] = 0.f;

    for (int kt = 0; kt < SEQ; kt += 64) {
        __syncthreads();
        // stage K and V^T tiles (hi/lo)
#pragma unroll
        for (int l = 0; l < 4; l++) {
            int id  = tid + l * 128;
            int row = id >> 3;
            int dc  = (id & 7) << 3;
            size_t ksrc = ((size_t)bh * SEQ + kt + row) * DK + dc;   // [key][d]
            *(uint4*)&Khi[row * FSTR + dc] = *(const uint4*)&g_k_hi[ksrc];
            *(uint4*)&Klo[row * FSTR + dc] = *(const uint4*)&g_k_lo[ksrc];
            size_t vsrc = ((size_t)bh * DK + row) * SEQ + kt + dc;   // [d][key]
            *(uint4*)&Vhi[row * FSTR + dc] = *(const uint4*)&g_vt_hi[vsrc];
            *(uint4*)&Vlo[row * FSTR + dc] = *(const uint4*)&g_vt_lo[vsrc];
        }
        __syncthreads();

        // ---- S = Q.K^T (3-pass split) ----
        float sacc[8][4];
#pragma unroll
        for (int j = 0; j < 8; j++)
#pragma unroll
            for (int r = 0; r < 4; r++) sacc[j][r] = 0.f;

#pragma unroll
        for (int j = 0; j < 8; j++) {
            int krow = (8 * j + g) * FSTR;
#pragma unroll
            for (int t = 0; t < 4; t++) {
                int c0 = 16 * t + 2 * tq;
                uint32_t bhf[2], blf[2];
                bhf[0] = *(const uint32_t*)&Khi[krow + c0];
                bhf[1] = *(const uint32_t*)&Khi[krow + c0 + 8];
                blf[0] = *(const uint32_t*)&Klo[krow + c0];
                blf[1] = *(const uint32_t*)&Klo[krow + c0 + 8];
                mma16816(sacc[j], aqh[t], bhf);
                mma16816(sacc[j], aqh[t], blf);
                mma16816(sacc[j], aql[t], bhf);
            }
        }

        // ---- online softmax (rows g and g+8; quad lanes share a row) ----
        float mx0 = -1e30f, mx1 = -1e30f;
#pragma unroll
        for (int j = 0; j < 8; j++) {
            mx0 = fmaxf(mx0, fmaxf(sacc[j][0], sacc[j][1]));
            mx1 = fmaxf(mx1, fmaxf(sacc[j][2], sacc[j][3]));
        }
#pragma unroll
        for (int off = 1; off <= 2; off <<= 1) {
            mx0 = fmaxf(mx0, __shfl_xor_sync(0xffffffffu, mx0, off));
            mx1 = fmaxf(mx1, __shfl_xor_sync(0xffffffffu, mx1, off));
        }
        float mn0 = fmaxf(m0, mx0), mn1 = fmaxf(m1, mx1);
        float al0 = __expf(m0 - mn0), al1 = __expf(m1 - mn1);
        m0 = mn0; m1 = mn1;

        float rs0 = 0.f, rs1 = 0.f;
#pragma unroll
        for (int j = 0; j < 8; j++) {
            sacc[j][0] = __expf(sacc[j][0] - mn0);
            sacc[j][1] = __expf(sacc[j][1] - mn0);
            sacc[j][2] = __expf(sacc[j][2] - mn1);
            sacc[j][3] = __expf(sacc[j][3] - mn1);
            rs0 += sacc[j][0] + sacc[j][1];
            rs1 += sacc[j][2] + sacc[j][3];
        }
#pragma unroll
        for (int off = 1; off <= 2; off <<= 1) {
            rs0 += __shfl_xor_sync(0xffffffffu, rs0, off);
            rs1 += __shfl_xor_sync(0xffffffffu, rs1, off);
        }
        l0 = l0 * al0 + rs0;
        l1 = l1 * al1 + rs1;
#pragma unroll
        for (int dj = 0; dj < 8; dj++) {
            oacc[dj][0] *= al0; oacc[dj][1] *= al0;
            oacc[dj][2] *= al1; oacc[dj][3] *= al1;
        }

        // ---- P -> split bf16 A-fragments (FA2 register permutation) ----
        uint32_t pah[4][4], pal[4][4];
#pragma unroll
        for (int t = 0; t < 4; t++) {
            split_pack2(sacc[2*t    ][0], sacc[2*t    ][1], pah[t][0], pal[t][0]);
            split_pack2(sacc[2*t    ][2], sacc[2*t    ][3], pah[t][1], pal[t][1]);
            split_pack2(sacc[2*t + 1][0], sacc[2*t + 1][1], pah[t][2], pal[t][2]);
            split_pack2(sacc[2*t + 1][2], sacc[2*t + 1][3], pah[t][3], pal[t][3]);
        }

        // ---- O += P.V (3-pass split) ----
#pragma unroll
        for (int dj = 0; dj < 8; dj++) {
            int vrow = (8 * dj + g) * FSTR;
#pragma unroll
            for (int t = 0; t < 4; t++) {
                int c0 = 16 * t + 2 * tq;
                uint32_t bhf[2], blf[2];
                bhf[0] = *(const uint32_t*)&Vhi[vrow + c0];
                bhf[1] = *(const uint32_t*)&Vhi[vrow + c0 + 8];
                blf[0] = *(const uint32_t*)&Vlo[vrow + c0];
                blf[1] = *(const uint32_t*)&Vlo[vrow + c0 + 8];
                mma16816(oacc[dj], pah[t], bhf);
                mma16816(oacc[dj], pah[t], blf);
                mma16816(oacc[dj], pal[t], bhf);
            }
        }
    }

    // epilogue: normalize, write concat layout [B,S,H*DK]
    float inv0 = 1.f / l0, inv1 = 1.f / l1;
    int s0 = qbase + q0 + g;
    int s1 = s0 + 8;
#pragma unroll
    for (int dj = 0; dj < 8; dj++) {
        int d = h * DK + 8 * dj + 2 * tq;
        float2 r0 = make_float2(oacc[dj][0] * inv0, oacc[dj][1] * inv0);
        float2 r1 = make_float2(oacc[dj][2] * inv1, oacc[dj][3] * inv1);
        *(float2*)&g_ctx[(size_t)(b * SEQ + s0) * D_MODEL + d] = r0;
        *(float2*)&g_ctx[(size_t)(b * SEQ + s1) * D_MODEL + d] = r1;
    }
}

// ---------------- launch ----------------------------------------------------
extern "C" void kernel_launch(void* const* d_in, const int* in_sizes, int n_in,
                              void* d_out, int out_size)
{
    const float* q  = (const float*)d_in[0];
    const float* k  = (const float*)d_in[1];
    const float* v  = (const float*)d_in[2];
    const float* wq = (const float*)d_in[3];
    const float* bq = (const float*)d_in[4];
    const float* wk = (const float*)d_in[5];
    const float* bk = (const float*)d_in[6];
    const float* wv = (const float*)d_in[7];
    const float* bv = (const float*)d_in[8];
    const float* wo = (const float*)d_in[9];
    const float* bo = (const float*)d_in[10];
    float* out = (float*)d_out;

    dim3 gemm_grid(D_MODEL / BN, M_TOK / BM);   // (8, 32)

    mma_gemm_bias_k<<<gemm_grid, 256>>>(q, wq, bq, nullptr, 0);
    mma_gemm_bias_k<<<gemm_grid, 256>>>(k, wk, bk, nullptr, 1);
    mma_gemm_bias_k<<<gemm_grid, 256>>>(v, wv, bv, nullptr, 2);

    vtrans_k<<<dim3(SEQ / 32, BH), 256>>>();

    const int fa_smem = 6 * 64 * FSTR * (int)sizeof(uint16_t);   // 55296
    cudaFuncSetAttribute(flash_mma_k,
                         cudaFuncAttributeMaxDynamicSharedMemorySize, fa_smem);
    flash_mma_k<<<dim3(SEQ / 64, BH), 128, fa_smem>>>();

    mma_gemm_bias_k<<<gemm_grid, 256>>>(nullptr, wo, bo, out, 3);
}